// round 12
// baseline (speedup 1.0000x reference)
#include <cuda_runtime.h>
#include <cstdint>

// Inv1x1MM_SVD, C=16, 65536 positions.
// WARP-SPECIALIZED: warp pair shares 16 positions. Even warp: QR(U) and
// w = (data.Q0)*rs0*exp(ls) -> smem. Odd warp (parallel): QR(V), rs1 -> smem;
// after a named 64-thread barrier it computes res = sum_j w_j*rs1_j*b1_j.
// Per-warp register peak is ONE 16x16 matrix (~115 regs) -> 4 blocks/SM.
// Within a warp: 2 lanes per position, lane (pos,half) holds 8 rows packed
// as f32x2 column pairs (proven R6/R10 layout; fresh norms for stability).

constexpr int NPOS = 8 * 8192;

#define FMA2(d, a, b, c) asm("fma.rn.f32x2 %0, %1, %2, %3;" : "=l"(d) : "l"(a), "l"(b), "l"(c))
#define MUL2(d, a, b)    asm("mul.rn.f32x2 %0, %1, %2;"     : "=l"(d) : "l"(a), "l"(b))
#define ADD2(d, a, b)    asm("add.rn.f32x2 %0, %1, %2;"     : "=l"(d) : "l"(a), "l"(b))
#define PACK2(d, lo, hi) asm("mov.b64 %0, {%1, %2};"        : "=l"(d) : "f"(lo), "f"(hi))
#define UNPACK2(lo, hi, d) asm("mov.b64 {%0, %1}, %2;" : "=f"(lo), "=f"(hi) : "l"(d))

__device__ __forceinline__ uint64_t shx1(uint64_t v) {
    uint32_t lo, hi;
    asm("mov.b64 {%0, %1}, %2;" : "=r"(lo), "=r"(hi) : "l"(v));
    lo = __shfl_xor_sync(0xffffffffu, lo, 1);
    hi = __shfl_xor_sync(0xffffffffu, hi, 1);
    uint64_t r;
    asm("mov.b64 %0, {%1, %2};" : "=l"(r) : "r"(lo), "r"(hi));
    return r;
}
__device__ __forceinline__ float frcp(float x) {
    float r;
    asm("rcp.approx.f32 %0, %1;" : "=f"(r) : "f"(x));
    return r;
}

// MGS, rows split across a lane pair; writer lane stores 1/||b_k|| to sm[k].
__device__ __forceinline__ void mgs2(uint64_t (&A)[8][8], float* sm, bool writer) {
    #pragma unroll
    for (int k = 0; k < 15; k++) {
        const int c0 = k >> 1;
        const int cu = (k + 1) >> 1;

        uint64_t ak[8];
        #pragma unroll
        for (int i = 0; i < 8; i++) {
            float lo, hi;
            UNPACK2(lo, hi, A[i][c0]);
            const float x = (k & 1) ? hi : lo;
            PACK2(ak[i], x, x);
        }

        uint64_t pp[8];
        #pragma unroll
        for (int c = c0; c < 8; c++) {
            uint64_t s0, s1;
            MUL2(s0, ak[0], A[0][c]);
            MUL2(s1, ak[4], A[4][c]);
            FMA2(s0, ak[1], A[1][c], s0);
            FMA2(s1, ak[5], A[5][c], s1);
            FMA2(s0, ak[2], A[2][c], s0);
            FMA2(s1, ak[6], A[6][c], s1);
            FMA2(s0, ak[3], A[3][c], s0);
            FMA2(s1, ak[7], A[7][c], s1);
            ADD2(s0, s0, s1);
            const uint64_t o = shx1(s0);
            ADD2(pp[c], s0, o);
        }

        float plo, phi;
        UNPACK2(plo, phi, pp[c0]);
        const float pk = fmaxf((k & 1) ? phi : plo, 1e-30f);
        const float ninv = -frcp(pk);        // projection path (MUFU.RCP)
        const float r = rsqrtf(pk);          // normalization path (parallel)
        if (writer) sm[k] = r;
        uint64_t n2;
        PACK2(n2, ninv, ninv);

        #pragma unroll
        for (int c = cu; c < 8; c++) {
            uint64_t s;
            MUL2(s, pp[c], n2);
            if (!(k & 1) && c == cu) {       // pair contains j == k: mask lo half
                float sl, sh;
                UNPACK2(sl, sh, s);
                PACK2(s, 0.0f, sh);
            }
            #pragma unroll
            for (int i = 0; i < 8; i++) FMA2(A[i][c], s, ak[i], A[i][c]);
        }
    }
    float n15 = 0.0f;
    #pragma unroll
    for (int i = 0; i < 8; i++) {
        float lo, hi;
        UNPACK2(lo, hi, A[i][7]);
        n15 = fmaf(hi, hi, n15);
    }
    n15 += __shfl_xor_sync(0xffffffffu, n15, 1);
    if (writer) sm[15] = rsqrtf(fmaxf(n15, 1e-30f));
}

__device__ __forceinline__ void load_mat(uint64_t (&A)[8][8], const float4* f4, int rbase) {
    #pragma unroll
    for (int i = 0; i < 8; i++) {
        const float4 q0 = __ldg(&f4[rbase + 4 * i + 0]);
        const float4 q1 = __ldg(&f4[rbase + 4 * i + 1]);
        const float4 q2 = __ldg(&f4[rbase + 4 * i + 2]);
        const float4 q3 = __ldg(&f4[rbase + 4 * i + 3]);
        PACK2(A[i][0], q0.x, q0.y); PACK2(A[i][1], q0.z, q0.w);
        PACK2(A[i][2], q1.x, q1.y); PACK2(A[i][3], q1.z, q1.w);
        PACK2(A[i][4], q2.x, q2.y); PACK2(A[i][5], q2.z, q2.w);
        PACK2(A[i][6], q3.x, q3.y); PACK2(A[i][7], q3.z, q3.w);
    }
}

__global__ void __launch_bounds__(128, 4)
inv1x1mm_svd_kernel(const float* __restrict__ data,
                    const float* __restrict__ paras,
                    float* __restrict__ out) {
    // stride-18 rows: 8B-aligned float2 slots, conflict-free across the 16
    // positions of a warp (18p mod 32 distinct for p in 0..15).
    __shared__ __align__(8) float wsm[32][18];   // rs0 then w (U warp -> V warp)
    __shared__ __align__(8) float rsm[32][18];   // rs1 (V warp internal)

    const int tid    = threadIdx.x;
    const int warp   = tid >> 5;            // 0..3
    const int pairid = warp >> 1;           // 0..1 (16-position group)
    const int role   = warp & 1;            // 0 = U warp, 1 = V warp
    const int lane   = tid & 31;
    const int half   = lane & 1;
    const int p      = pairid * 16 + (lane >> 1);   // 0..31 within block
    const int pos    = blockIdx.x * 32 + p;

    const float4* f4 = (const float4*)(paras + (size_t)pos * 528);
    const bool writer = (half == 0);
    float* smw = &wsm[p][0];

    uint64_t A[8][8];

    if (role == 0) {
        // ===== QR of U =====  rs0 -> smw
        load_mat(A, f4, 4 + half * 32);
        mgs2(A, smw, writer);

        // v_j = <data, b0_j>: local partials then pair reduce
        const float4 d0 = __ldg((const float4*)(data + pos * 16 + half * 8));
        const float4 d1 = __ldg((const float4*)(data + pos * 16 + half * 8 + 4));
        uint64_t dd[8];
        PACK2(dd[0], d0.x, d0.x); PACK2(dd[1], d0.y, d0.y);
        PACK2(dd[2], d0.z, d0.z); PACK2(dd[3], d0.w, d0.w);
        PACK2(dd[4], d1.x, d1.x); PACK2(dd[5], d1.y, d1.y);
        PACK2(dd[6], d1.z, d1.z); PACK2(dd[7], d1.w, d1.w);

        __syncwarp();   // partner's rs0 stores -> my reads below
        #pragma unroll
        for (int c = 0; c < 8; c++) {
            uint64_t s0, s1;
            MUL2(s0, dd[0], A[0][c]);
            MUL2(s1, dd[4], A[4][c]);
            FMA2(s0, dd[1], A[1][c], s0);
            FMA2(s1, dd[5], A[5][c], s1);
            FMA2(s0, dd[2], A[2][c], s0);
            FMA2(s1, dd[6], A[6][c], s1);
            FMA2(s0, dd[3], A[3][c], s0);
            FMA2(s1, dd[7], A[7][c], s1);
            ADD2(s0, s0, s1);
            const uint64_t o = shx1(s0);
            ADD2(s0, s0, o);                       // full v pair
            const float2 lsp = __ldg((const float2*)(paras + (size_t)pos * 528 + 2 * c));
            const float2 rsp = *(const float2*)&smw[2 * c];   // rs0 pair
            uint64_t m;
            PACK2(m, __expf(lsp.x) * rsp.x, __expf(lsp.y) * rsp.y);
            MUL2(s0, s0, m);                       // w pair
            if (writer) {                          // overwrite slot with w
                float wl, wh;
                UNPACK2(wl, wh, s0);
                *(float2*)&smw[2 * c] = make_float2(wl, wh);
            }
        }
        // publish w to the V warp
        asm volatile("bar.sync %0, 64;" :: "r"(1 + pairid) : "memory");
    } else {
        // ===== QR of V =====  rs1 -> rsm   (runs concurrently with U warp)
        load_mat(A, f4, 68 + half * 32);
        mgs2(A, &rsm[p][0], writer);
        __syncwarp();   // partner's rs1 stores -> my epilogue reads

        // wait for w from the U warp
        asm volatile("bar.sync %0, 64;" :: "r"(1 + pairid) : "memory");

        // ww_j = w_j * rs1_j ; res_d = sum_j ww_j * b1[d][j] (my 8 rows)
        uint64_t ww[8];
        #pragma unroll
        for (int c = 0; c < 8; c++) {
            const float2 wv = *(const float2*)&smw[2 * c];
            const float2 rv = *(const float2*)&rsm[p][2 * c];
            PACK2(ww[c], wv.x * rv.x, wv.y * rv.y);
        }
        float o[8];
        #pragma unroll
        for (int i = 0; i < 8; i++) {
            uint64_t s0, s1;
            MUL2(s0, ww[0], A[i][0]);
            MUL2(s1, ww[4], A[i][4]);
            FMA2(s0, ww[1], A[i][1], s0);
            FMA2(s1, ww[5], A[i][5], s1);
            FMA2(s0, ww[2], A[i][2], s0);
            FMA2(s1, ww[6], A[i][6], s1);
            FMA2(s0, ww[3], A[i][3], s0);
            FMA2(s1, ww[7], A[i][7], s1);
            ADD2(s0, s0, s1);
            float lo, hi;
            UNPACK2(lo, hi, s0);
            o[i] = lo + hi;
        }
        float4* o4 = (float4*)(out + pos * 16 + half * 8);
        o4[0] = make_float4(o[0], o[1], o[2], o[3]);
        o4[1] = make_float4(o[4], o[5], o[6], o[7]);
    }
}

extern "C" void kernel_launch(void* const* d_in, const int* in_sizes, int n_in,
                              void* d_out, int out_size) {
    const float* data  = (const float*)d_in[0];
    const float* paras = (const float*)d_in[1];
    if (n_in >= 2 && in_sizes[0] > in_sizes[1]) {  // defensive ordering by size
        data  = (const float*)d_in[1];
        paras = (const float*)d_in[0];
    }
    inv1x1mm_svd_kernel<<<NPOS / 32, 128>>>(data, paras, (float*)d_out);
}

// round 13
// speedup vs baseline: 1.4442x; 1.4442x over previous
#include <cuda_runtime.h>
#include <cstdint>

// Inv1x1MM_SVD, C=16, 65536 positions.
// R10 compute (2-lane row-slab MGS, fresh norms, rs0->smem, rs1 folded into w)
// + coalesced shared-memory staging of paras. Direct slab LDGs touched 32
// lines per instruction (32 L1 wavefronts each) and drowned the L1tex queue;
// staging loads are coalesced (4 wf/instr) and slab reads become LDS.

constexpr int NPOS = 8 * 8192;

#define FMA2(d, a, b, c) asm("fma.rn.f32x2 %0, %1, %2, %3;" : "=l"(d) : "l"(a), "l"(b), "l"(c))
#define MUL2(d, a, b)    asm("mul.rn.f32x2 %0, %1, %2;"     : "=l"(d) : "l"(a), "l"(b))
#define ADD2(d, a, b)    asm("add.rn.f32x2 %0, %1, %2;"     : "=l"(d) : "l"(a), "l"(b))
#define PACK2(d, lo, hi) asm("mov.b64 %0, {%1, %2};"        : "=l"(d) : "f"(lo), "f"(hi))
#define UNPACK2(lo, hi, d) asm("mov.b64 {%0, %1}, %2;" : "=f"(lo), "=f"(hi) : "l"(d))

__device__ __forceinline__ uint64_t shx1(uint64_t v) {
    uint32_t lo, hi;
    asm("mov.b64 {%0, %1}, %2;" : "=r"(lo), "=r"(hi) : "l"(v));
    lo = __shfl_xor_sync(0xffffffffu, lo, 1);
    hi = __shfl_xor_sync(0xffffffffu, hi, 1);
    uint64_t r;
    asm("mov.b64 %0, {%1, %2};" : "=l"(r) : "r"(lo), "r"(hi));
    return r;
}
__device__ __forceinline__ float frcp(float x) {
    float r;
    asm("rcp.approx.f32 %0, %1;" : "=f"(r) : "f"(x));
    return r;
}

// MGS, rows split across a lane pair.
// SCALEW=false: writer lane stores 1/||b_k|| to rs_sm[k].
// SCALEW=true : fold 1/||b_k|| into w element k as columns finish.
template <bool SCALEW>
__device__ __forceinline__ void mgs2(uint64_t (&A)[8][8], uint64_t* w,
                                     float* rs_sm, bool writer) {
    #pragma unroll
    for (int k = 0; k < 15; k++) {
        const int c0 = k >> 1;
        const int cu = (k + 1) >> 1;

        uint64_t ak[8];
        #pragma unroll
        for (int i = 0; i < 8; i++) {
            float lo, hi;
            UNPACK2(lo, hi, A[i][c0]);
            const float x = (k & 1) ? hi : lo;
            PACK2(ak[i], x, x);
        }

        uint64_t pp[8];
        #pragma unroll
        for (int c = c0; c < 8; c++) {
            uint64_t s0, s1;
            MUL2(s0, ak[0], A[0][c]);
            MUL2(s1, ak[4], A[4][c]);
            FMA2(s0, ak[1], A[1][c], s0);
            FMA2(s1, ak[5], A[5][c], s1);
            FMA2(s0, ak[2], A[2][c], s0);
            FMA2(s1, ak[6], A[6][c], s1);
            FMA2(s0, ak[3], A[3][c], s0);
            FMA2(s1, ak[7], A[7][c], s1);
            ADD2(s0, s0, s1);
            const uint64_t o = shx1(s0);
            ADD2(pp[c], s0, o);
        }

        float plo, phi;
        UNPACK2(plo, phi, pp[c0]);
        const float pk = fmaxf((k & 1) ? phi : plo, 1e-30f);
        const float ninv = -frcp(pk);        // projection path (MUFU.RCP)
        const float r = rsqrtf(pk);          // normalization path (parallel)
        if (SCALEW) {
            float wl, wh;
            UNPACK2(wl, wh, w[c0]);
            if (k & 1) wh *= r; else wl *= r;
            PACK2(w[c0], wl, wh);
        } else if (writer) {
            rs_sm[k] = r;
        }
        uint64_t n2;
        PACK2(n2, ninv, ninv);

        #pragma unroll
        for (int c = cu; c < 8; c++) {
            uint64_t s;
            MUL2(s, pp[c], n2);
            if (!(k & 1) && c == cu) {       // pair contains j == k: mask lo half
                float sl, sh;
                UNPACK2(sl, sh, s);
                PACK2(s, 0.0f, sh);
            }
            #pragma unroll
            for (int i = 0; i < 8; i++) FMA2(A[i][c], s, ak[i], A[i][c]);
        }
    }
    float n15 = 0.0f;
    #pragma unroll
    for (int i = 0; i < 8; i++) {
        float lo, hi;
        UNPACK2(lo, hi, A[i][7]);
        n15 = fmaf(hi, hi, n15);
    }
    n15 += __shfl_xor_sync(0xffffffffu, n15, 1);
    const float r = rsqrtf(fmaxf(n15, 1e-30f));
    if (SCALEW) {
        float wl, wh;
        UNPACK2(wl, wh, w[7]);
        wh *= r;
        PACK2(w[7], wl, wh);
    } else if (writer) {
        rs_sm[15] = r;
    }
}

// load my 8-row slab from the staged smem buffer (row = float4 bufrow[.])
__device__ __forceinline__ void load_mat_sm(uint64_t (&A)[8][8],
                                            const float4* bufrow, int rbase) {
    #pragma unroll
    for (int i = 0; i < 8; i++) {
        const float4 q0 = bufrow[rbase + 4 * i + 0];
        const float4 q1 = bufrow[rbase + 4 * i + 1];
        const float4 q2 = bufrow[rbase + 4 * i + 2];
        const float4 q3 = bufrow[rbase + 4 * i + 3];
        PACK2(A[i][0], q0.x, q0.y); PACK2(A[i][1], q0.z, q0.w);
        PACK2(A[i][2], q1.x, q1.y); PACK2(A[i][3], q1.z, q1.w);
        PACK2(A[i][4], q2.x, q2.y); PACK2(A[i][5], q2.z, q2.w);
        PACK2(A[i][6], q3.x, q3.y); PACK2(A[i][7], q3.z, q3.w);
    }
}

__global__ void __launch_bounds__(64, 6)
inv1x1mm_svd_kernel(const float* __restrict__ data,
                    const float* __restrict__ paras,
                    float* __restrict__ out) {
    __shared__ float4 buf[32][69];            // staged ls+U (68 f4/pos), then V (64)
    __shared__ float rs_sm[32][17];           // U inverse norms, stride-17

    const int tid  = threadIdx.x;
    const int half = tid & 1;
    const int p    = tid >> 1;
    const int posbase = blockIdx.x * 32;
    const int pos  = posbase + p;

    const float4* g4 = (const float4*)paras + (size_t)posbase * 132;

    // ---- stage ls+U for all 32 positions, coalesced (2176 float4) ----
    #pragma unroll
    for (int it = 0; it < 34; it++) {
        const int L  = it * 64 + tid;
        const int pp = L / 68;
        const int f  = L - pp * 68;
        buf[pp][f] = __ldg(&g4[(size_t)pp * 132 + f]);
    }
    __syncthreads();

    uint64_t A[8][8];

    // ===== QR of U =====  (slab read from smem; rs0 -> rs_sm)
    load_mat_sm(A, &buf[p][0], 4 + half * 32);
    mgs2<false>(A, nullptr, rs_sm[p], half == 0);

    // local partial dots v_j against U's Q
    const float4 d0 = __ldg((const float4*)(data + pos * 16 + half * 8));
    const float4 d1 = __ldg((const float4*)(data + pos * 16 + half * 8 + 4));
    uint64_t dd[8];
    PACK2(dd[0], d0.x, d0.x); PACK2(dd[1], d0.y, d0.y);
    PACK2(dd[2], d0.z, d0.z); PACK2(dd[3], d0.w, d0.w);
    PACK2(dd[4], d1.x, d1.x); PACK2(dd[5], d1.y, d1.y);
    PACK2(dd[6], d1.z, d1.z); PACK2(dd[7], d1.w, d1.w);

    uint64_t w[8];
    #pragma unroll
    for (int c = 0; c < 8; c++) {
        uint64_t s0, s1;
        MUL2(s0, dd[0], A[0][c]);
        MUL2(s1, dd[4], A[4][c]);
        FMA2(s0, dd[1], A[1][c], s0);
        FMA2(s1, dd[5], A[5][c], s1);
        FMA2(s0, dd[2], A[2][c], s0);
        FMA2(s1, dd[6], A[6][c], s1);
        FMA2(s0, dd[3], A[3][c], s0);
        FMA2(s1, dd[7], A[7][c], s1);
        ADD2(w[c], s0, s1);
    }

    __syncwarp();   // partner's rs_sm writes -> my reads
    const float* lsrow = (const float*)&buf[p][0];
    #pragma unroll
    for (int c = 0; c < 8; c++) {
        const uint64_t o = shx1(w[c]);
        ADD2(w[c], w[c], o);
        const float2 lsp = *(const float2*)&lsrow[2 * c];   // ls pair from smem
        uint64_t m;
        PACK2(m, __expf(lsp.x) * rs_sm[p][2 * c],
                 __expf(lsp.y) * rs_sm[p][2 * c + 1]);
        MUL2(w[c], w[c], m);
    }

    // ---- stage V for all 32 positions, coalesced (2048 float4) ----
    __syncthreads();   // everyone done reading ls+U from buf
    #pragma unroll
    for (int it = 0; it < 32; it++) {
        const int L  = it * 64 + tid;
        const int pp = L >> 6;
        const int f  = L & 63;
        buf[pp][f] = __ldg(&g4[(size_t)pp * 132 + 68 + f]);
    }
    __syncthreads();

    // ===== QR of V =====  (folds 1/||b1_j|| into w)
    load_mat_sm(A, &buf[p][0], half * 32);
    mgs2<true>(A, w, nullptr, false);

    // res_d = sum_j w_j * b1[d][j]  (d = my 8 local rows)
    float o[8];
    #pragma unroll
    for (int i = 0; i < 8; i++) {
        uint64_t s0, s1;
        MUL2(s0, w[0], A[i][0]);
        MUL2(s1, w[4], A[i][4]);
        FMA2(s0, w[1], A[i][1], s0);
        FMA2(s1, w[5], A[i][5], s1);
        FMA2(s0, w[2], A[i][2], s0);
        FMA2(s1, w[6], A[i][6], s1);
        FMA2(s0, w[3], A[i][3], s0);
        FMA2(s1, w[7], A[i][7], s1);
        ADD2(s0, s0, s1);
        float lo, hi;
        UNPACK2(lo, hi, s0);
        o[i] = lo + hi;
    }

    float4* o4 = (float4*)(out + pos * 16 + half * 8);
    o4[0] = make_float4(o[0], o[1], o[2], o[3]);
    o4[1] = make_float4(o[4], o[5], o[6], o[7]);
}

extern "C" void kernel_launch(void* const* d_in, const int* in_sizes, int n_in,
                              void* d_out, int out_size) {
    const float* data  = (const float*)d_in[0];
    const float* paras = (const float*)d_in[1];
    if (n_in >= 2 && in_sizes[0] > in_sizes[1]) {  // defensive ordering by size
        data  = (const float*)d_in[1];
        paras = (const float*)d_in[0];
    }
    inv1x1mm_svd_kernel<<<NPOS / 32, 64>>>(data, paras, (float*)d_out);
}